// round 8
// baseline (speedup 1.0000x reference)
#include <cuda_runtime.h>

// Fixed shapes: B=4, C=256, H=W=160, CPS=16 -> nv=nh=10, N=100, NPAT=400/branch
#define HH   160
#define WW   160
#define CC   256
#define NPAT 400
#define ENC  128

__device__ float g_conv_out[2 * NPAT * 256];   // [branch][patch][pix]
__device__ float g_h1[2 * NPAT * 256];         // hidden activations
__device__ float g_emb[2 * NPAT * ENC];        // [branch][patch][enc]

__device__ __forceinline__ void pdl_wait() {
    asm volatile("griddepcontrol.wait;" ::: "memory");
}

// ---------------------------------------------------------------------------
// Kernel A: channel-reduce conv + bias + relu. K split 4 ways (measured best).
// 800 blocks x 256 threads; block = 64 float4 outputs of one branch.
// ---------------------------------------------------------------------------
__global__ void __launch_bounds__(256) conv_kernel(
    const float* __restrict__ f1, const float* __restrict__ f2,
    const float* __restrict__ w_img, const float* __restrict__ b_img,
    const float* __restrict__ w_dep, const float* __restrict__ b_dep)
{
    __shared__ float  ws[256];
    __shared__ float4 part[4][64];
    __shared__ float  bias_s;

    const int t      = threadIdx.x;
    const int branch = blockIdx.x / 400;
    const int item0  = (blockIdx.x % 400) * 64;

    const float* wsrc = branch ? w_dep : w_img;
    ws[t] = wsrc[t];
    if (t == 0) bias_s = branch ? b_dep[0] : b_img[0];
    __syncthreads();

    const int kg = t >> 6;        // channel group 0..3
    const int ol = t & 63;
    const int r  = item0 + ol;    // 0..25599 (float4 items per branch)
    const int b  = r / 6400;      // 160*40 float4 per image
    const int r2 = r % 6400;
    const int h  = r2 / 40;
    const int w0 = (r2 % 40) * 4;

    const float* feat  = branch ? f2 : f1;
    const float4* base = (const float4*)(feat + (size_t)b * CC * HH * WW + h * WW + w0)
                         + (size_t)kg * 64 * 6400;   // channel stride = 6400 f4

    float4 acc = make_float4(0.f, 0.f, 0.f, 0.f);
    #pragma unroll 16
    for (int c = 0; c < 64; c++) {
        float4 v = base[c * 6400];
        float wc = ws[kg * 64 + c];
        acc.x = fmaf(v.x, wc, acc.x);
        acc.y = fmaf(v.y, wc, acc.y);
        acc.z = fmaf(v.z, wc, acc.z);
        acc.w = fmaf(v.w, wc, acc.w);
    }
    part[kg][ol] = acc;
    __syncthreads();

    if (t < 64) {
        float4 p0 = part[0][t], p1 = part[1][t], p2 = part[2][t], p3 = part[3][t];
        const float bb = bias_s;
        float4 o4;
        o4.x = fmaxf(p0.x + p1.x + p2.x + p3.x + bb, 0.f);
        o4.y = fmaxf(p0.y + p1.y + p2.y + p3.y + bb, 0.f);
        o4.z = fmaxf(p0.z + p1.z + p2.z + p3.z + bb, 0.f);
        o4.w = fmaxf(p0.w + p1.w + p2.w + p3.w + bb, 0.f);

        const int rr  = item0 + t;
        const int bb2 = rr / 6400;
        const int rr2 = rr % 6400;
        const int hh  = rr2 / 40;
        const int ww0 = (rr2 % 40) * 4;
        const int p   = bb2 * 100 + (hh >> 4) * 10 + (ww0 >> 4);
        const int pix = (hh & 15) * 16 + (ww0 & 15);
        *(float4*)&g_conv_out[(size_t)branch * NPAT * 256 + p * 256 + pix] = o4;
    }
}

// ---------------------------------------------------------------------------
// Kernel B1: GEMM1 + relu.  h1[p][o] = relu( x[p] . w1[o] ),  o in [0,256)
// Grid 200 = branch(2) x out-tile(4, 64 wide) x patch-tile(25, 16 tall).
// 128 threads. PDL: weight tile (independent of conv) loads BEFORE the
// griddepcontrol.wait; activation tile after.
// ---------------------------------------------------------------------------
#define G1_SMEM_BYTES ((256 * 17 + 256 * 64) * 4)

__global__ void __launch_bounds__(128) gemm1_kernel(
    const float* __restrict__ w1_img, const float* __restrict__ w1_dep)
{
    extern __shared__ float sm[];
    float* as_ = sm;             // [256][17]   asT[k][p]
    float* ws_ = sm + 256 * 17;  // [256][64]   swizzled wsT[k][o]

    const int t      = threadIdx.x;
    const int branch = blockIdx.x / 100;
    const int rr     = blockIdx.x % 100;
    const int ot     = rr & 3;
    const int pt     = rr >> 2;
    const int p0     = branch * NPAT + pt * 16;
    const int o0     = ot * 64;

    const float* w1 = branch ? w1_dep : w1_img;

    // --- W tile first (does NOT depend on conv output) ---
    {
        const int k4 = t & 63;
        const int og = t >> 6;   // 0..1
        #pragma unroll
        for (int j = 0; j < 8; j++) {
            const int ob = og * 32 + j * 4;
            const int o4 = og * 8 + j;
            float4 v0 = *(const float4*)&w1[(size_t)(o0 + ob + 0) * 256 + k4 * 4];
            float4 v1 = *(const float4*)&w1[(size_t)(o0 + ob + 1) * 256 + k4 * 4];
            float4 v2 = *(const float4*)&w1[(size_t)(o0 + ob + 2) * 256 + k4 * 4];
            float4 v3 = *(const float4*)&w1[(size_t)(o0 + ob + 3) * 256 + k4 * 4];
            float4 t0 = make_float4(v0.x, v1.x, v2.x, v3.x);
            float4 t1 = make_float4(v0.y, v1.y, v2.y, v3.y);
            float4 t2 = make_float4(v0.z, v1.z, v2.z, v3.z);
            float4 t3 = make_float4(v0.w, v1.w, v2.w, v3.w);
            const int kb = k4 * 4;
            *(float4*)&ws_[(kb + 0) * 64 + ((o4 ^ ((kb + 0) & 15)) << 2)] = t0;
            *(float4*)&ws_[(kb + 1) * 64 + ((o4 ^ ((kb + 1) & 15)) << 2)] = t1;
            *(float4*)&ws_[(kb + 2) * 64 + ((o4 ^ ((kb + 2) & 15)) << 2)] = t2;
            *(float4*)&ws_[(kb + 3) * 64 + ((o4 ^ ((kb + 3) & 15)) << 2)] = t3;
        }
    }

    pdl_wait();   // conv output now visible

    // --- A tile (16 x 256), transpose to asT[k][p] ---
    #pragma unroll
    for (int j = 0; j < 8; j++) {
        const int idx4 = j * 128 + t;
        const int p    = idx4 >> 6;
        const int k4   = idx4 & 63;
        float4 v = *(const float4*)&g_conv_out[(size_t)(p0 + p) * 256 + k4 * 4];
        as_[(k4 * 4 + 0) * 17 + p] = v.x;
        as_[(k4 * 4 + 1) * 17 + p] = v.y;
        as_[(k4 * 4 + 2) * 17 + p] = v.z;
        as_[(k4 * 4 + 3) * 17 + p] = v.w;
    }
    __syncthreads();

    const int ox = t & 15;
    const int py = t >> 4;   // 0..7 -> patches 2py, 2py+1
    float a00 = 0.f, a01 = 0.f, a02 = 0.f, a03 = 0.f;
    float a10 = 0.f, a11 = 0.f, a12 = 0.f, a13 = 0.f;
    #pragma unroll 8
    for (int k = 0; k < 256; k++) {
        const float4 wv = *(const float4*)&ws_[k * 64 + ((ox ^ (k & 15)) << 2)];
        const float  x0 = as_[k * 17 + py * 2];
        const float  x1 = as_[k * 17 + py * 2 + 1];
        a00 = fmaf(x0, wv.x, a00); a01 = fmaf(x0, wv.y, a01);
        a02 = fmaf(x0, wv.z, a02); a03 = fmaf(x0, wv.w, a03);
        a10 = fmaf(x1, wv.x, a10); a11 = fmaf(x1, wv.y, a11);
        a12 = fmaf(x1, wv.z, a12); a13 = fmaf(x1, wv.w, a13);
    }
    const int gp = p0 + py * 2;
    float4 r0 = make_float4(fmaxf(a00, 0.f), fmaxf(a01, 0.f), fmaxf(a02, 0.f), fmaxf(a03, 0.f));
    float4 r1 = make_float4(fmaxf(a10, 0.f), fmaxf(a11, 0.f), fmaxf(a12, 0.f), fmaxf(a13, 0.f));
    *(float4*)&g_h1[(size_t)gp * 256 + o0 + ox * 4]       = r0;
    *(float4*)&g_h1[(size_t)(gp + 1) * 256 + o0 + ox * 4] = r1;
}

// ---------------------------------------------------------------------------
// Kernel B2: GEMM2 + LayerNorm.  y[p][o] = h1[p] . w2[o],  o in [0,128)
// Grid 100 = branch(2) x patch-tile(50, 8 tall). 128 threads.
// PDL: full W2 loads before the wait; h1 tile after.
// ---------------------------------------------------------------------------
#define G2_SMEM_BYTES ((256 * 9 + 256 * 128) * 4)

__global__ void __launch_bounds__(128) gemm2_kernel(
    const float* __restrict__ w2_img, const float* __restrict__ g_img,
    const float* __restrict__ be_img,
    const float* __restrict__ w2_dep, const float* __restrict__ g_dep,
    const float* __restrict__ be_dep)
{
    extern __shared__ float sm[];
    float* as_ = sm;             // [256][9]
    float* ws_ = sm + 256 * 9;   // [256][128] swizzled

    const int t      = threadIdx.x;
    const int branch = blockIdx.x / 50;
    const int pt     = blockIdx.x % 50;
    const int p0     = branch * NPAT + pt * 8;

    const float* w2 = branch ? w2_dep : w2_img;

    // --- full W2 (128 x 256) first (independent of gemm1) ---
    {
        const int k4 = t & 63;
        const int og = t >> 6;   // 0..1
        #pragma unroll
        for (int j = 0; j < 16; j++) {
            const int ob = og * 64 + j * 4;
            const int o4 = og * 16 + j;
            float4 v0 = *(const float4*)&w2[(size_t)(ob + 0) * 256 + k4 * 4];
            float4 v1 = *(const float4*)&w2[(size_t)(ob + 1) * 256 + k4 * 4];
            float4 v2 = *(const float4*)&w2[(size_t)(ob + 2) * 256 + k4 * 4];
            float4 v3 = *(const float4*)&w2[(size_t)(ob + 3) * 256 + k4 * 4];
            float4 t0 = make_float4(v0.x, v1.x, v2.x, v3.x);
            float4 t1 = make_float4(v0.y, v1.y, v2.y, v3.y);
            float4 t2 = make_float4(v0.z, v1.z, v2.z, v3.z);
            float4 t3 = make_float4(v0.w, v1.w, v2.w, v3.w);
            const int kb = k4 * 4;
            *(float4*)&ws_[(kb + 0) * 128 + ((o4 ^ ((kb + 0) & 31)) << 2)] = t0;
            *(float4*)&ws_[(kb + 1) * 128 + ((o4 ^ ((kb + 1) & 31)) << 2)] = t1;
            *(float4*)&ws_[(kb + 2) * 128 + ((o4 ^ ((kb + 2) & 31)) << 2)] = t2;
            *(float4*)&ws_[(kb + 3) * 128 + ((o4 ^ ((kb + 3) & 31)) << 2)] = t3;
        }
    }

    pdl_wait();   // gemm1 output now visible

    // --- A tile (8 x 256) transposed ---
    #pragma unroll
    for (int j = 0; j < 4; j++) {
        const int idx4 = j * 128 + t;
        const int p    = idx4 >> 6;
        const int k4   = idx4 & 63;
        float4 v = *(const float4*)&g_h1[(size_t)(p0 + p) * 256 + k4 * 4];
        as_[(k4 * 4 + 0) * 9 + p] = v.x;
        as_[(k4 * 4 + 1) * 9 + p] = v.y;
        as_[(k4 * 4 + 2) * 9 + p] = v.z;
        as_[(k4 * 4 + 3) * 9 + p] = v.w;
    }
    __syncthreads();

    const int ox = t & 31;   // lane
    const int py = t >> 5;   // warp -> patches 2py, 2py+1
    float a00 = 0.f, a01 = 0.f, a02 = 0.f, a03 = 0.f;
    float a10 = 0.f, a11 = 0.f, a12 = 0.f, a13 = 0.f;
    #pragma unroll 4
    for (int k = 0; k < 256; k++) {
        const float4 wv = *(const float4*)&ws_[k * 128 + ((ox ^ (k & 31)) << 2)];
        const float  x0 = as_[k * 9 + py * 2];
        const float  x1 = as_[k * 9 + py * 2 + 1];
        a00 = fmaf(x0, wv.x, a00); a01 = fmaf(x0, wv.y, a01);
        a02 = fmaf(x0, wv.z, a02); a03 = fmaf(x0, wv.w, a03);
        a10 = fmaf(x1, wv.x, a10); a11 = fmaf(x1, wv.y, a11);
        a12 = fmaf(x1, wv.z, a12); a13 = fmaf(x1, wv.w, a13);
    }

    float sA = a00 + a01 + a02 + a03;
    float qA = a00 * a00 + a01 * a01 + a02 * a02 + a03 * a03;
    float sB = a10 + a11 + a12 + a13;
    float qB = a10 * a10 + a11 * a11 + a12 * a12 + a13 * a13;
    #pragma unroll
    for (int off = 16; off > 0; off >>= 1) {
        sA += __shfl_xor_sync(0xffffffffu, sA, off);
        qA += __shfl_xor_sync(0xffffffffu, qA, off);
        sB += __shfl_xor_sync(0xffffffffu, sB, off);
        qB += __shfl_xor_sync(0xffffffffu, qB, off);
    }
    const float mA = sA * (1.f / 128.f);
    const float mB = sB * (1.f / 128.f);
    const float rA = rsqrtf(qA * (1.f / 128.f) - mA * mA + 1e-5f);
    const float rB = rsqrtf(qB * (1.f / 128.f) - mB * mB + 1e-5f);

    const float* lg = branch ? g_dep  : g_img;
    const float* lb = branch ? be_dep : be_img;
    const float4 gv = *(const float4*)&lg[ox * 4];
    const float4 bv = *(const float4*)&lb[ox * 4];

    float4 oA, oB;
    oA.x = (a00 - mA) * rA * gv.x + bv.x;  oA.y = (a01 - mA) * rA * gv.y + bv.y;
    oA.z = (a02 - mA) * rA * gv.z + bv.z;  oA.w = (a03 - mA) * rA * gv.w + bv.w;
    oB.x = (a10 - mB) * rB * gv.x + bv.x;  oB.y = (a11 - mB) * rB * gv.y + bv.y;
    oB.z = (a12 - mB) * rB * gv.z + bv.z;  oB.w = (a13 - mB) * rB * gv.w + bv.w;

    const int gp = p0 + py * 2;
    *(float4*)&g_emb[(size_t)gp * 128 + ox * 4]       = oA;
    *(float4*)&g_emb[(size_t)(gp + 1) * 128 + ox * 4] = oB;
}

// ---------------------------------------------------------------------------
// Kernel C: logits (R6 measured-best form). Grid (25, 4) x 128 threads.
// 4 e1 rows in smem; thread t = m reads its e2 row via LDG.128 (L2-resident).
// ---------------------------------------------------------------------------
__global__ void __launch_bounds__(128) logits_kernel(
    const float* __restrict__ logit_scale, float* __restrict__ out)
{
    __shared__ float e1s[4][128];

    const int t  = threadIdx.x;
    const int b  = blockIdx.y;
    const int n0 = blockIdx.x * 4;

    pdl_wait();   // gemm2 output now visible

    {
        const int r  = t >> 5;
        const int c4 = t & 31;
        *(float4*)&e1s[r][c4 * 4] =
            *(const float4*)&g_emb[(size_t)(b * 100 + n0 + r) * 128 + c4 * 4];
    }
    __syncthreads();

    if (t < 100) {
        const float scale = expf(logit_scale[0]);
        const float4* e2r = (const float4*)&g_emb[(size_t)(NPAT + b * 100 + t) * 128];
        float a0 = 0.f, a1 = 0.f, a2 = 0.f, a3 = 0.f;
        #pragma unroll 8
        for (int d4 = 0; d4 < 32; d4++) {
            const float4 c  = e2r[d4];
            const float4 e0 = *(const float4*)&e1s[0][d4 * 4];
            const float4 e1 = *(const float4*)&e1s[1][d4 * 4];
            const float4 e2 = *(const float4*)&e1s[2][d4 * 4];
            const float4 e3 = *(const float4*)&e1s[3][d4 * 4];
            a0 = fmaf(e0.x, c.x, a0); a0 = fmaf(e0.y, c.y, a0);
            a0 = fmaf(e0.z, c.z, a0); a0 = fmaf(e0.w, c.w, a0);
            a1 = fmaf(e1.x, c.x, a1); a1 = fmaf(e1.y, c.y, a1);
            a1 = fmaf(e1.z, c.z, a1); a1 = fmaf(e1.w, c.w, a1);
            a2 = fmaf(e2.x, c.x, a2); a2 = fmaf(e2.y, c.y, a2);
            a2 = fmaf(e2.z, c.z, a2); a2 = fmaf(e2.w, c.w, a2);
            a3 = fmaf(e3.x, c.x, a3); a3 = fmaf(e3.y, c.y, a3);
            a3 = fmaf(e3.z, c.z, a3); a3 = fmaf(e3.w, c.w, a3);
        }
        const float v0 = scale * a0;
        const float v1 = scale * a1;
        const float v2 = scale * a2;
        const float v3 = scale * a3;
        float* o1 = out + b * 10000;
        float* o2 = out + 40000 + b * 10000;
        o1[(n0 + 0) * 100 + t] = v0;
        o1[(n0 + 1) * 100 + t] = v1;
        o1[(n0 + 2) * 100 + t] = v2;
        o1[(n0 + 3) * 100 + t] = v3;
        o2[t * 100 + n0 + 0] = v0;
        o2[t * 100 + n0 + 1] = v1;
        o2[t * 100 + n0 + 2] = v2;
        o2[t * 100 + n0 + 3] = v3;
    }
}

// ---------------------------------------------------------------------------
// Inputs: feat_c1, feat_c2, mask_c1, img_conv_w, img_conv_b, img_w1, img_w2,
// img_ln_g, img_ln_b, depth_conv_w, depth_conv_b, depth_w1, depth_w2,
// depth_ln_g, depth_ln_b, logit_scale
// ---------------------------------------------------------------------------
extern "C" void kernel_launch(void* const* d_in, const int* in_sizes, int n_in,
                              void* d_out, int out_size)
{
    cudaFuncSetAttribute(gemm1_kernel, cudaFuncAttributeMaxDynamicSharedMemorySize, G1_SMEM_BYTES);
    cudaFuncSetAttribute(gemm2_kernel, cudaFuncAttributeMaxDynamicSharedMemorySize, G2_SMEM_BYTES);

    conv_kernel<<<800, 256>>>((const float*)d_in[0], (const float*)d_in[1],
                              (const float*)d_in[3],  (const float*)d_in[4],
                              (const float*)d_in[9],  (const float*)d_in[10]);

    // Dependent kernels launched with programmatic stream serialization (PDL):
    // their prologues (weight smem loads) overlap the predecessor's drain.
    cudaLaunchAttribute pdl_attr[1];
    pdl_attr[0].id = cudaLaunchAttributeProgrammaticStreamSerialization;
    pdl_attr[0].val.programmaticStreamSerializationAllowed = 1;

    {
        cudaLaunchConfig_t cfg = {};
        cfg.gridDim = dim3(200, 1, 1);
        cfg.blockDim = dim3(128, 1, 1);
        cfg.dynamicSmemBytes = G1_SMEM_BYTES;
        cfg.stream = 0;
        cfg.attrs = pdl_attr;
        cfg.numAttrs = 1;
        cudaLaunchKernelEx(&cfg, gemm1_kernel,
                           (const float*)d_in[5], (const float*)d_in[11]);
    }
    {
        cudaLaunchConfig_t cfg = {};
        cfg.gridDim = dim3(100, 1, 1);
        cfg.blockDim = dim3(128, 1, 1);
        cfg.dynamicSmemBytes = G2_SMEM_BYTES;
        cfg.stream = 0;
        cfg.attrs = pdl_attr;
        cfg.numAttrs = 1;
        cudaLaunchKernelEx(&cfg, gemm2_kernel,
                           (const float*)d_in[6],  (const float*)d_in[7],
                           (const float*)d_in[8],
                           (const float*)d_in[12], (const float*)d_in[13],
                           (const float*)d_in[14]);
    }
    {
        cudaLaunchConfig_t cfg = {};
        cfg.gridDim = dim3(25, 4, 1);
        cfg.blockDim = dim3(128, 1, 1);
        cfg.dynamicSmemBytes = 0;
        cfg.stream = 0;
        cfg.attrs = pdl_attr;
        cfg.numAttrs = 1;
        cudaLaunchKernelEx(&cfg, logits_kernel,
                           (const float*)d_in[15], (float*)d_out);
    }
}

// round 9
// speedup vs baseline: 1.1566x; 1.1566x over previous
#include <cuda_runtime.h>

// Fixed shapes: B=4, C=256, H=W=160, CPS=16 -> nv=nh=10, N=100, NPAT=400/branch
#define HH   160
#define WW   160
#define CC   256
#define NPAT 400
#define ENC  128

__device__ float g_conv_out[2 * NPAT * 256];   // [branch][patch][pix]
__device__ float g_h1[2 * NPAT * 256];         // hidden activations
__device__ float g_emb[2 * NPAT * ENC];        // [branch][patch][enc]

// ---------------------------------------------------------------------------
// Kernel A: channel-reduce conv + bias + relu. K split 4 ways (measured best:
// 37.4us @ 72% DRAM in R3). 800 blocks x 256 threads; block = 64 f4 outputs.
// ---------------------------------------------------------------------------
__global__ void __launch_bounds__(256) conv_kernel(
    const float* __restrict__ f1, const float* __restrict__ f2,
    const float* __restrict__ w_img, const float* __restrict__ b_img,
    const float* __restrict__ w_dep, const float* __restrict__ b_dep)
{
    __shared__ float  ws[256];
    __shared__ float4 part[4][64];
    __shared__ float  bias_s;

    const int t      = threadIdx.x;
    const int branch = blockIdx.x / 400;
    const int item0  = (blockIdx.x % 400) * 64;

    const float* wsrc = branch ? w_dep : w_img;
    ws[t] = wsrc[t];
    if (t == 0) bias_s = branch ? b_dep[0] : b_img[0];
    __syncthreads();

    const int kg = t >> 6;        // channel group 0..3
    const int ol = t & 63;
    const int r  = item0 + ol;    // 0..25599 (float4 items per branch)
    const int b  = r / 6400;      // 160*40 float4 per image
    const int r2 = r % 6400;
    const int h  = r2 / 40;
    const int w0 = (r2 % 40) * 4;

    const float* feat  = branch ? f2 : f1;
    const float4* base = (const float4*)(feat + (size_t)b * CC * HH * WW + h * WW + w0)
                         + (size_t)kg * 64 * 6400;   // channel stride = 6400 f4

    float4 acc = make_float4(0.f, 0.f, 0.f, 0.f);
    #pragma unroll 16
    for (int c = 0; c < 64; c++) {
        float4 v = base[c * 6400];
        float wc = ws[kg * 64 + c];
        acc.x = fmaf(v.x, wc, acc.x);
        acc.y = fmaf(v.y, wc, acc.y);
        acc.z = fmaf(v.z, wc, acc.z);
        acc.w = fmaf(v.w, wc, acc.w);
    }
    part[kg][ol] = acc;
    __syncthreads();

    if (t < 64) {
        float4 p0 = part[0][t], p1 = part[1][t], p2 = part[2][t], p3 = part[3][t];
        const float bb = bias_s;
        float4 o4;
        o4.x = fmaxf(p0.x + p1.x + p2.x + p3.x + bb, 0.f);
        o4.y = fmaxf(p0.y + p1.y + p2.y + p3.y + bb, 0.f);
        o4.z = fmaxf(p0.z + p1.z + p2.z + p3.z + bb, 0.f);
        o4.w = fmaxf(p0.w + p1.w + p2.w + p3.w + bb, 0.f);

        const int rr  = item0 + t;
        const int bb2 = rr / 6400;
        const int rr2 = rr % 6400;
        const int hh  = rr2 / 40;
        const int ww0 = (rr2 % 40) * 4;
        const int p   = bb2 * 100 + (hh >> 4) * 10 + (ww0 >> 4);
        const int pix = (hh & 15) * 16 + (ww0 & 15);
        *(float4*)&g_conv_out[(size_t)branch * NPAT * 256 + p * 256 + pix] = o4;
    }
}

// ---------------------------------------------------------------------------
// Kernel B1: GEMM1 + relu.  h1[p][o] = relu( x[p] . w1[o] ),  o in [0,256)
// Grid 200 = branch(2) x out-tile(4, 64 wide) x patch-tile(25, 16 tall).
// 128 threads: ox = t&15 (4 outputs), py = t>>4 (2 patches) -> 8 FMA per wv.
// ---------------------------------------------------------------------------
#define G1_SMEM_BYTES ((256 * 17 + 256 * 64) * 4)

__global__ void __launch_bounds__(128) gemm1_kernel(
    const float* __restrict__ w1_img, const float* __restrict__ w1_dep)
{
    extern __shared__ float sm[];
    float* as_ = sm;             // [256][17]   asT[k][p]
    float* ws_ = sm + 256 * 17;  // [256][64]   swizzled wsT[k][o]

    const int t      = threadIdx.x;
    const int branch = blockIdx.x / 100;
    const int rr     = blockIdx.x % 100;
    const int ot     = rr & 3;
    const int pt     = rr >> 2;
    const int p0     = branch * NPAT + pt * 16;
    const int o0     = ot * 64;

    const float* w1 = branch ? w1_dep : w1_img;

    #pragma unroll
    for (int j = 0; j < 8; j++) {
        const int idx4 = j * 128 + t;
        const int p    = idx4 >> 6;
        const int k4   = idx4 & 63;
        float4 v = *(const float4*)&g_conv_out[(size_t)(p0 + p) * 256 + k4 * 4];
        as_[(k4 * 4 + 0) * 17 + p] = v.x;
        as_[(k4 * 4 + 1) * 17 + p] = v.y;
        as_[(k4 * 4 + 2) * 17 + p] = v.z;
        as_[(k4 * 4 + 3) * 17 + p] = v.w;
    }
    {
        const int k4 = t & 63;
        const int og = t >> 6;   // 0..1
        #pragma unroll
        for (int j = 0; j < 8; j++) {
            const int ob = og * 32 + j * 4;
            const int o4 = og * 8 + j;
            float4 v0 = *(const float4*)&w1[(size_t)(o0 + ob + 0) * 256 + k4 * 4];
            float4 v1 = *(const float4*)&w1[(size_t)(o0 + ob + 1) * 256 + k4 * 4];
            float4 v2 = *(const float4*)&w1[(size_t)(o0 + ob + 2) * 256 + k4 * 4];
            float4 v3 = *(const float4*)&w1[(size_t)(o0 + ob + 3) * 256 + k4 * 4];
            float4 t0 = make_float4(v0.x, v1.x, v2.x, v3.x);
            float4 t1 = make_float4(v0.y, v1.y, v2.y, v3.y);
            float4 t2 = make_float4(v0.z, v1.z, v2.z, v3.z);
            float4 t3 = make_float4(v0.w, v1.w, v2.w, v3.w);
            const int kb = k4 * 4;
            *(float4*)&ws_[(kb + 0) * 64 + ((o4 ^ ((kb + 0) & 15)) << 2)] = t0;
            *(float4*)&ws_[(kb + 1) * 64 + ((o4 ^ ((kb + 1) & 15)) << 2)] = t1;
            *(float4*)&ws_[(kb + 2) * 64 + ((o4 ^ ((kb + 2) & 15)) << 2)] = t2;
            *(float4*)&ws_[(kb + 3) * 64 + ((o4 ^ ((kb + 3) & 15)) << 2)] = t3;
        }
    }
    __syncthreads();

    const int ox = t & 15;
    const int py = t >> 4;   // 0..7 -> patches 2py, 2py+1
    float a00 = 0.f, a01 = 0.f, a02 = 0.f, a03 = 0.f;
    float a10 = 0.f, a11 = 0.f, a12 = 0.f, a13 = 0.f;
    #pragma unroll 8
    for (int k = 0; k < 256; k++) {
        const float4 wv = *(const float4*)&ws_[k * 64 + ((ox ^ (k & 15)) << 2)];
        const float  x0 = as_[k * 17 + py * 2];
        const float  x1 = as_[k * 17 + py * 2 + 1];
        a00 = fmaf(x0, wv.x, a00); a01 = fmaf(x0, wv.y, a01);
        a02 = fmaf(x0, wv.z, a02); a03 = fmaf(x0, wv.w, a03);
        a10 = fmaf(x1, wv.x, a10); a11 = fmaf(x1, wv.y, a11);
        a12 = fmaf(x1, wv.z, a12); a13 = fmaf(x1, wv.w, a13);
    }
    const int gp = p0 + py * 2;
    float4 r0 = make_float4(fmaxf(a00, 0.f), fmaxf(a01, 0.f), fmaxf(a02, 0.f), fmaxf(a03, 0.f));
    float4 r1 = make_float4(fmaxf(a10, 0.f), fmaxf(a11, 0.f), fmaxf(a12, 0.f), fmaxf(a13, 0.f));
    *(float4*)&g_h1[(size_t)gp * 256 + o0 + ox * 4]       = r0;
    *(float4*)&g_h1[(size_t)(gp + 1) * 256 + o0 + ox * 4] = r1;
}

// ---------------------------------------------------------------------------
// Kernel B2: GEMM2 + LayerNorm.  y[p][o] = h1[p] . w2[o],  o in [0,128)
// Grid 100 = branch(2) x patch-tile(50, 8 tall). 128 threads.
// ---------------------------------------------------------------------------
#define G2_SMEM_BYTES ((256 * 9 + 256 * 128) * 4)

__global__ void __launch_bounds__(128) gemm2_kernel(
    const float* __restrict__ w2_img, const float* __restrict__ g_img,
    const float* __restrict__ be_img,
    const float* __restrict__ w2_dep, const float* __restrict__ g_dep,
    const float* __restrict__ be_dep)
{
    extern __shared__ float sm[];
    float* as_ = sm;             // [256][9]
    float* ws_ = sm + 256 * 9;   // [256][128] swizzled

    const int t      = threadIdx.x;
    const int branch = blockIdx.x / 50;
    const int pt     = blockIdx.x % 50;
    const int p0     = branch * NPAT + pt * 8;

    const float* w2 = branch ? w2_dep : w2_img;

    #pragma unroll
    for (int j = 0; j < 4; j++) {
        const int idx4 = j * 128 + t;
        const int p    = idx4 >> 6;
        const int k4   = idx4 & 63;
        float4 v = *(const float4*)&g_h1[(size_t)(p0 + p) * 256 + k4 * 4];
        as_[(k4 * 4 + 0) * 9 + p] = v.x;
        as_[(k4 * 4 + 1) * 9 + p] = v.y;
        as_[(k4 * 4 + 2) * 9 + p] = v.z;
        as_[(k4 * 4 + 3) * 9 + p] = v.w;
    }
    {
        const int k4 = t & 63;
        const int og = t >> 6;   // 0..1
        #pragma unroll
        for (int j = 0; j < 16; j++) {
            const int ob = og * 64 + j * 4;
            const int o4 = og * 16 + j;
            float4 v0 = *(const float4*)&w2[(size_t)(ob + 0) * 256 + k4 * 4];
            float4 v1 = *(const float4*)&w2[(size_t)(ob + 1) * 256 + k4 * 4];
            float4 v2 = *(const float4*)&w2[(size_t)(ob + 2) * 256 + k4 * 4];
            float4 v3 = *(const float4*)&w2[(size_t)(ob + 3) * 256 + k4 * 4];
            float4 t0 = make_float4(v0.x, v1.x, v2.x, v3.x);
            float4 t1 = make_float4(v0.y, v1.y, v2.y, v3.y);
            float4 t2 = make_float4(v0.z, v1.z, v2.z, v3.z);
            float4 t3 = make_float4(v0.w, v1.w, v2.w, v3.w);
            const int kb = k4 * 4;
            *(float4*)&ws_[(kb + 0) * 128 + ((o4 ^ ((kb + 0) & 31)) << 2)] = t0;
            *(float4*)&ws_[(kb + 1) * 128 + ((o4 ^ ((kb + 1) & 31)) << 2)] = t1;
            *(float4*)&ws_[(kb + 2) * 128 + ((o4 ^ ((kb + 2) & 31)) << 2)] = t2;
            *(float4*)&ws_[(kb + 3) * 128 + ((o4 ^ ((kb + 3) & 31)) << 2)] = t3;
        }
    }
    __syncthreads();

    const int ox = t & 31;   // lane
    const int py = t >> 5;   // warp -> patches 2py, 2py+1
    float a00 = 0.f, a01 = 0.f, a02 = 0.f, a03 = 0.f;
    float a10 = 0.f, a11 = 0.f, a12 = 0.f, a13 = 0.f;
    #pragma unroll 4
    for (int k = 0; k < 256; k++) {
        const float4 wv = *(const float4*)&ws_[k * 128 + ((ox ^ (k & 31)) << 2)];
        const float  x0 = as_[k * 9 + py * 2];
        const float  x1 = as_[k * 9 + py * 2 + 1];
        a00 = fmaf(x0, wv.x, a00); a01 = fmaf(x0, wv.y, a01);
        a02 = fmaf(x0, wv.z, a02); a03 = fmaf(x0, wv.w, a03);
        a10 = fmaf(x1, wv.x, a10); a11 = fmaf(x1, wv.y, a11);
        a12 = fmaf(x1, wv.z, a12); a13 = fmaf(x1, wv.w, a13);
    }

    float sA = a00 + a01 + a02 + a03;
    float qA = a00 * a00 + a01 * a01 + a02 * a02 + a03 * a03;
    float sB = a10 + a11 + a12 + a13;
    float qB = a10 * a10 + a11 * a11 + a12 * a12 + a13 * a13;
    #pragma unroll
    for (int off = 16; off > 0; off >>= 1) {
        sA += __shfl_xor_sync(0xffffffffu, sA, off);
        qA += __shfl_xor_sync(0xffffffffu, qA, off);
        sB += __shfl_xor_sync(0xffffffffu, sB, off);
        qB += __shfl_xor_sync(0xffffffffu, qB, off);
    }
    const float mA = sA * (1.f / 128.f);
    const float mB = sB * (1.f / 128.f);
    const float rA = rsqrtf(qA * (1.f / 128.f) - mA * mA + 1e-5f);
    const float rB = rsqrtf(qB * (1.f / 128.f) - mB * mB + 1e-5f);

    const float* lg = branch ? g_dep  : g_img;
    const float* lb = branch ? be_dep : be_img;
    const float4 gv = *(const float4*)&lg[ox * 4];
    const float4 bv = *(const float4*)&lb[ox * 4];

    float4 oA, oB;
    oA.x = (a00 - mA) * rA * gv.x + bv.x;  oA.y = (a01 - mA) * rA * gv.y + bv.y;
    oA.z = (a02 - mA) * rA * gv.z + bv.z;  oA.w = (a03 - mA) * rA * gv.w + bv.w;
    oB.x = (a10 - mB) * rB * gv.x + bv.x;  oB.y = (a11 - mB) * rB * gv.y + bv.y;
    oB.z = (a12 - mB) * rB * gv.z + bv.z;  oB.w = (a13 - mB) * rB * gv.w + bv.w;

    const int gp = p0 + py * 2;
    *(float4*)&g_emb[(size_t)gp * 128 + ox * 4]       = oA;
    *(float4*)&g_emb[(size_t)(gp + 1) * 128 + ox * 4] = oB;
}

// ---------------------------------------------------------------------------
// Kernel C: logits (R6 measured-best form). Grid (25, 4) x 128 threads.
// 4 e1 rows in smem; thread t = m reads its e2 row via LDG.128 (L2-resident).
// ---------------------------------------------------------------------------
__global__ void __launch_bounds__(128) logits_kernel(
    const float* __restrict__ logit_scale, float* __restrict__ out)
{
    __shared__ float e1s[4][128];

    const int t  = threadIdx.x;
    const int b  = blockIdx.y;
    const int n0 = blockIdx.x * 4;

    {
        const int r  = t >> 5;
        const int c4 = t & 31;
        *(float4*)&e1s[r][c4 * 4] =
            *(const float4*)&g_emb[(size_t)(b * 100 + n0 + r) * 128 + c4 * 4];
    }
    __syncthreads();

    if (t < 100) {
        const float scale = expf(logit_scale[0]);
        const float4* e2r = (const float4*)&g_emb[(size_t)(NPAT + b * 100 + t) * 128];
        float a0 = 0.f, a1 = 0.f, a2 = 0.f, a3 = 0.f;
        #pragma unroll 8
        for (int d4 = 0; d4 < 32; d4++) {
            const float4 c  = e2r[d4];
            const float4 e0 = *(const float4*)&e1s[0][d4 * 4];
            const float4 e1 = *(const float4*)&e1s[1][d4 * 4];
            const float4 e2 = *(const float4*)&e1s[2][d4 * 4];
            const float4 e3 = *(const float4*)&e1s[3][d4 * 4];
            a0 = fmaf(e0.x, c.x, a0); a0 = fmaf(e0.y, c.y, a0);
            a0 = fmaf(e0.z, c.z, a0); a0 = fmaf(e0.w, c.w, a0);
            a1 = fmaf(e1.x, c.x, a1); a1 = fmaf(e1.y, c.y, a1);
            a1 = fmaf(e1.z, c.z, a1); a1 = fmaf(e1.w, c.w, a1);
            a2 = fmaf(e2.x, c.x, a2); a2 = fmaf(e2.y, c.y, a2);
            a2 = fmaf(e2.z, c.z, a2); a2 = fmaf(e2.w, c.w, a2);
            a3 = fmaf(e3.x, c.x, a3); a3 = fmaf(e3.y, c.y, a3);
            a3 = fmaf(e3.z, c.z, a3); a3 = fmaf(e3.w, c.w, a3);
        }
        const float v0 = scale * a0;
        const float v1 = scale * a1;
        const float v2 = scale * a2;
        const float v3 = scale * a3;
        float* o1 = out + b * 10000;
        float* o2 = out + 40000 + b * 10000;
        o1[(n0 + 0) * 100 + t] = v0;
        o1[(n0 + 1) * 100 + t] = v1;
        o1[(n0 + 2) * 100 + t] = v2;
        o1[(n0 + 3) * 100 + t] = v3;
        o2[t * 100 + n0 + 0] = v0;
        o2[t * 100 + n0 + 1] = v1;
        o2[t * 100 + n0 + 2] = v2;
        o2[t * 100 + n0 + 3] = v3;
    }
}

// ---------------------------------------------------------------------------
// Inputs: feat_c1, feat_c2, mask_c1, img_conv_w, img_conv_b, img_w1, img_w2,
// img_ln_g, img_ln_b, depth_conv_w, depth_conv_b, depth_w1, depth_w2,
// depth_ln_g, depth_ln_b, logit_scale
// ---------------------------------------------------------------------------
extern "C" void kernel_launch(void* const* d_in, const int* in_sizes, int n_in,
                              void* d_out, int out_size)
{
    cudaFuncSetAttribute(gemm1_kernel, cudaFuncAttributeMaxDynamicSharedMemorySize, G1_SMEM_BYTES);
    cudaFuncSetAttribute(gemm2_kernel, cudaFuncAttributeMaxDynamicSharedMemorySize, G2_SMEM_BYTES);

    conv_kernel<<<800, 256>>>((const float*)d_in[0], (const float*)d_in[1],
                              (const float*)d_in[3],  (const float*)d_in[4],
                              (const float*)d_in[9],  (const float*)d_in[10]);

    gemm1_kernel<<<200, 128, G1_SMEM_BYTES>>>((const float*)d_in[5], (const float*)d_in[11]);

    gemm2_kernel<<<100, 128, G2_SMEM_BYTES>>>((const float*)d_in[6],  (const float*)d_in[7],
                                              (const float*)d_in[8],
                                              (const float*)d_in[12], (const float*)d_in[13],
                                              (const float*)d_in[14]);

    logits_kernel<<<dim3(25, 4), 128>>>((const float*)d_in[15], (float*)d_out);
}

// round 10
// speedup vs baseline: 1.2970x; 1.1214x over previous
#include <cuda_runtime.h>

// Fixed shapes: B=4, C=256, H=W=160, CPS=16 -> nv=nh=10, N=100, NPAT=400/branch
#define HH   160
#define WW   160
#define CC   256
#define NPAT 400
#define ENC  128

__device__ float g_conv_out[2 * NPAT * 256];   // [branch][patch][pix]
__device__ float g_emb[2 * NPAT * ENC];        // [branch][patch][enc]

// ---------------------------------------------------------------------------
// Kernel A: channel-reduce conv + bias + relu. K split 4 ways (measured best).
// 800 blocks x 256 threads; block = 64 f4 outputs of one branch.
// ---------------------------------------------------------------------------
__global__ void __launch_bounds__(256) conv_kernel(
    const float* __restrict__ f1, const float* __restrict__ f2,
    const float* __restrict__ w_img, const float* __restrict__ b_img,
    const float* __restrict__ w_dep, const float* __restrict__ b_dep)
{
    __shared__ float  ws[256];
    __shared__ float4 part[4][64];
    __shared__ float  bias_s;

    const int t      = threadIdx.x;
    const int branch = blockIdx.x / 400;
    const int item0  = (blockIdx.x % 400) * 64;

    const float* wsrc = branch ? w_dep : w_img;
    ws[t] = wsrc[t];
    if (t == 0) bias_s = branch ? b_dep[0] : b_img[0];
    __syncthreads();

    const int kg = t >> 6;        // channel group 0..3
    const int ol = t & 63;
    const int r  = item0 + ol;    // 0..25599 (float4 items per branch)
    const int b  = r / 6400;      // 160*40 float4 per image
    const int r2 = r % 6400;
    const int h  = r2 / 40;
    const int w0 = (r2 % 40) * 4;

    const float* feat  = branch ? f2 : f1;
    const float4* base = (const float4*)(feat + (size_t)b * CC * HH * WW + h * WW + w0)
                         + (size_t)kg * 64 * 6400;   // channel stride = 6400 f4

    float4 acc = make_float4(0.f, 0.f, 0.f, 0.f);
    #pragma unroll 16
    for (int c = 0; c < 64; c++) {
        float4 v = base[c * 6400];
        float wc = ws[kg * 64 + c];
        acc.x = fmaf(v.x, wc, acc.x);
        acc.y = fmaf(v.y, wc, acc.y);
        acc.z = fmaf(v.z, wc, acc.z);
        acc.w = fmaf(v.w, wc, acc.w);
    }
    part[kg][ol] = acc;
    __syncthreads();

    if (t < 64) {
        float4 p0 = part[0][t], p1 = part[1][t], p2 = part[2][t], p3 = part[3][t];
        const float bb = bias_s;
        float4 o4;
        o4.x = fmaxf(p0.x + p1.x + p2.x + p3.x + bb, 0.f);
        o4.y = fmaxf(p0.y + p1.y + p2.y + p3.y + bb, 0.f);
        o4.z = fmaxf(p0.z + p1.z + p2.z + p3.z + bb, 0.f);
        o4.w = fmaxf(p0.w + p1.w + p2.w + p3.w + bb, 0.f);

        const int rr  = item0 + t;
        const int bb2 = rr / 6400;
        const int rr2 = rr % 6400;
        const int hh  = rr2 / 40;
        const int ww0 = (rr2 % 40) * 4;
        const int p   = bb2 * 100 + (hh >> 4) * 10 + (ww0 >> 4);
        const int pix = (hh & 15) * 16 + (ww0 & 15);
        *(float4*)&g_conv_out[(size_t)branch * NPAT * 256 + p * 256 + pix] = o4;
    }
}

// ---------------------------------------------------------------------------
// Kernel B: fully fused MLP + LayerNorm. 100 blocks x 256 threads,
// 8 patches/block (block i -> global patches 8i..8i+7; branch = i/50).
// 3 phases of 128 outputs: W1[0:128], W1[128:256], W2[0:128]. Each phase
// streams a 128KB swizzled weight tile ([256][128], XOR over 32 f4 cols).
// Thread (ox=t&31: 4 outs, pg=(t>>5)&1: 4 patches, kq=t>>6: 64-k quarter):
// 16 FMA per wv LDS.128. k-quarter partials combined via smem (stride 20,
// odd-f4 -> conflict-free). h1 kept in smem transposed h1T[k][p] (pitch 12).
// LN at the end: warp w owns patch w.
// smem floats: ws 32768 | asT 3072 | h1T 3072 | red 5120 | ys 1056
// ---------------------------------------------------------------------------
#define MLP_SMEM_FLOATS (32768 + 3072 + 3072 + 5120 + 1056)
#define MLP_SMEM_BYTES  (MLP_SMEM_FLOATS * 4)

__global__ void __launch_bounds__(256) mlp_kernel(
    const float* __restrict__ w1_img, const float* __restrict__ w2_img,
    const float* __restrict__ g_img,  const float* __restrict__ be_img,
    const float* __restrict__ w1_dep, const float* __restrict__ w2_dep,
    const float* __restrict__ g_dep,  const float* __restrict__ be_dep)
{
    extern __shared__ float sm[];
    float* ws_ = sm;                       // [256][128] swizzled weight tile
    float* asT = sm + 32768;               // [256][12]  x transposed
    float* h1T = sm + 32768 + 3072;        // [256][12]  h1 transposed
    float* red = sm + 32768 + 6144;        // [256 threads][20]
    float* ys  = sm + 32768 + 6144 + 5120; // [8][132]

    const int t      = threadIdx.x;
    const int branch = blockIdx.x / 50;
    const int p0     = blockIdx.x * 8;     // global patch base (0..792)

    const float* w1 = branch ? w1_dep : w1_img;
    const float* w2 = branch ? w2_dep : w2_img;

    // --- load asT[k][p] from g_conv_out (8 patches x 256) ---
    #pragma unroll
    for (int j = 0; j < 2; j++) {
        const int idx4 = j * 256 + t;      // 0..511
        const int p    = idx4 >> 6;        // 0..7
        const int k4   = idx4 & 63;
        float4 v = *(const float4*)&g_conv_out[(size_t)(p0 + p) * 256 + k4 * 4];
        asT[(k4 * 4 + 0) * 12 + p] = v.x;
        asT[(k4 * 4 + 1) * 12 + p] = v.y;
        asT[(k4 * 4 + 2) * 12 + p] = v.z;
        asT[(k4 * 4 + 3) * 12 + p] = v.w;
    }

    const int ox = t & 31;         // 4 outputs  ox*4..ox*4+3
    const int pg = (t >> 5) & 1;   // patches pg*4..pg*4+3
    const int kq = t >> 6;         // k-quarter

    #pragma unroll 1
    for (int phase = 0; phase < 3; phase++) {
        const float* wsrc = (phase == 0) ? w1 : (phase == 1 ? w1 + 128 * 256 : w2);

        // --- stream 128x256 weight tile, 4x4 reg transpose, swizzled store ---
        {
            const int k4 = t & 63;
            const int og = t >> 6;   // 0..3
            #pragma unroll
            for (int j = 0; j < 8; j++) {
                const int ob = og * 32 + j * 4;
                const int o4 = og * 8 + j;     // 0..31
                float4 v0 = *(const float4*)&wsrc[(size_t)(ob + 0) * 256 + k4 * 4];
                float4 v1 = *(const float4*)&wsrc[(size_t)(ob + 1) * 256 + k4 * 4];
                float4 v2 = *(const float4*)&wsrc[(size_t)(ob + 2) * 256 + k4 * 4];
                float4 v3 = *(const float4*)&wsrc[(size_t)(ob + 3) * 256 + k4 * 4];
                float4 t0 = make_float4(v0.x, v1.x, v2.x, v3.x);
                float4 t1 = make_float4(v0.y, v1.y, v2.y, v3.y);
                float4 t2 = make_float4(v0.z, v1.z, v2.z, v3.z);
                float4 t3 = make_float4(v0.w, v1.w, v2.w, v3.w);
                const int kb = k4 * 4;
                *(float4*)&ws_[(kb + 0) * 128 + ((o4 ^ ((kb + 0) & 31)) << 2)] = t0;
                *(float4*)&ws_[(kb + 1) * 128 + ((o4 ^ ((kb + 1) & 31)) << 2)] = t1;
                *(float4*)&ws_[(kb + 2) * 128 + ((o4 ^ ((kb + 2) & 31)) << 2)] = t2;
                *(float4*)&ws_[(kb + 3) * 128 + ((o4 ^ ((kb + 3) & 31)) << 2)] = t3;
            }
        }
        __syncthreads();

        // --- compute: 4 outs x 4 patches over this thread's 64-k quarter ---
        const float* xsrc = (phase < 2) ? asT : h1T;
        float a00 = 0.f, a01 = 0.f, a02 = 0.f, a03 = 0.f;   // oi=0, pi 0..3
        float a10 = 0.f, a11 = 0.f, a12 = 0.f, a13 = 0.f;   // oi=1
        float a20 = 0.f, a21 = 0.f, a22 = 0.f, a23 = 0.f;   // oi=2
        float a30 = 0.f, a31 = 0.f, a32 = 0.f, a33 = 0.f;   // oi=3
        const int kbase = kq * 64;
        #pragma unroll 8
        for (int kk = 0; kk < 64; kk++) {
            const int k = kbase + kk;
            const float4 wv = *(const float4*)&ws_[k * 128 + ((ox ^ (k & 31)) << 2)];
            const float4 xv = *(const float4*)&xsrc[k * 12 + pg * 4];   // broadcast
            a00 = fmaf(wv.x, xv.x, a00); a01 = fmaf(wv.x, xv.y, a01);
            a02 = fmaf(wv.x, xv.z, a02); a03 = fmaf(wv.x, xv.w, a03);
            a10 = fmaf(wv.y, xv.x, a10); a11 = fmaf(wv.y, xv.y, a11);
            a12 = fmaf(wv.y, xv.z, a12); a13 = fmaf(wv.y, xv.w, a13);
            a20 = fmaf(wv.z, xv.x, a20); a21 = fmaf(wv.z, xv.y, a21);
            a22 = fmaf(wv.z, xv.z, a22); a23 = fmaf(wv.z, xv.w, a23);
            a30 = fmaf(wv.w, xv.x, a30); a31 = fmaf(wv.w, xv.y, a31);
            a32 = fmaf(wv.w, xv.z, a32); a33 = fmaf(wv.w, xv.w, a33);
        }
        // red[t][oi*4+pi], stride 20 floats (5 f4, odd -> conflict-free STS.128)
        *(float4*)&red[t * 20 +  0] = make_float4(a00, a01, a02, a03);
        *(float4*)&red[t * 20 +  4] = make_float4(a10, a11, a12, a13);
        *(float4*)&red[t * 20 +  8] = make_float4(a20, a21, a22, a23);
        *(float4*)&red[t * 20 + 12] = make_float4(a30, a31, a32, a33);
        __syncthreads();

        // --- combine k-quarters: 1024 outputs, 4 per thread ---
        #pragma unroll
        for (int rr = 0; rr < 4; rr++) {
            const int fidx = rr * 256 + t;       // 0..1023
            const int hi   = fidx >> 4;          // pg*32 + ox  (0..63)
            const int lo   = fidx & 15;          // oi*4 + pi
            float s = red[(0 * 64 + hi) * 20 + lo]
                    + red[(1 * 64 + hi) * 20 + lo]
                    + red[(2 * 64 + hi) * 20 + lo]
                    + red[(3 * 64 + hi) * 20 + lo];
            const int o = (hi & 31) * 4 + (lo >> 2);    // 0..127
            const int p = (hi >> 5) * 4 + (lo & 3);     // 0..7
            if (phase == 0)      h1T[o * 12 + p]         = fmaxf(s, 0.f);
            else if (phase == 1) h1T[(128 + o) * 12 + p] = fmaxf(s, 0.f);
            else                 ys[p * 132 + o]         = s;
        }
        __syncthreads();
    }

    // --- LayerNorm: warp w -> patch w ---
    {
        const int wid  = t >> 5;
        const int lane = t & 31;
        const float* yr = ys + wid * 132;
        float v0 = yr[lane], v1 = yr[lane + 32], v2 = yr[lane + 64], v3 = yr[lane + 96];
        float s  = v0 + v1 + v2 + v3;
        float ss = v0 * v0 + v1 * v1 + v2 * v2 + v3 * v3;
        #pragma unroll
        for (int off = 16; off > 0; off >>= 1) {
            s  += __shfl_xor_sync(0xffffffffu, s,  off);
            ss += __shfl_xor_sync(0xffffffffu, ss, off);
        }
        const float mean = s * (1.f / 128.f);
        const float var  = ss * (1.f / 128.f) - mean * mean;
        const float rstd = rsqrtf(var + 1e-5f);
        const float* lg = branch ? g_dep  : g_img;
        const float* lb = branch ? be_dep : be_img;
        float* outp = g_emb + (size_t)(p0 + wid) * 128;
        outp[lane]      = (v0 - mean) * rstd * lg[lane]      + lb[lane];
        outp[lane + 32] = (v1 - mean) * rstd * lg[lane + 32] + lb[lane + 32];
        outp[lane + 64] = (v2 - mean) * rstd * lg[lane + 64] + lb[lane + 64];
        outp[lane + 96] = (v3 - mean) * rstd * lg[lane + 96] + lb[lane + 96];
    }
}

// ---------------------------------------------------------------------------
// Kernel C: logits (measured-best form). Grid (25, 4) x 128 threads.
// 4 e1 rows in smem; thread t = m reads its e2 row via LDG.128 (L2-resident).
// ---------------------------------------------------------------------------
__global__ void __launch_bounds__(128) logits_kernel(
    const float* __restrict__ logit_scale, float* __restrict__ out)
{
    __shared__ float e1s[4][128];

    const int t  = threadIdx.x;
    const int b  = blockIdx.y;
    const int n0 = blockIdx.x * 4;

    {
        const int r  = t >> 5;
        const int c4 = t & 31;
        *(float4*)&e1s[r][c4 * 4] =
            *(const float4*)&g_emb[(size_t)(b * 100 + n0 + r) * 128 + c4 * 4];
    }
    __syncthreads();

    if (t < 100) {
        const float scale = expf(logit_scale[0]);
        const float4* e2r = (const float4*)&g_emb[(size_t)(NPAT + b * 100 + t) * 128];
        float a0 = 0.f, a1 = 0.f, a2 = 0.f, a3 = 0.f;
        #pragma unroll 8
        for (int d4 = 0; d4 < 32; d4++) {
            const float4 c  = e2r[d4];
            const float4 e0 = *(const float4*)&e1s[0][d4 * 4];
            const float4 e1 = *(const float4*)&e1s[1][d4 * 4];
            const float4 e2 = *(const float4*)&e1s[2][d4 * 4];
            const float4 e3 = *(const float4*)&e1s[3][d4 * 4];
            a0 = fmaf(e0.x, c.x, a0); a0 = fmaf(e0.y, c.y, a0);
            a0 = fmaf(e0.z, c.z, a0); a0 = fmaf(e0.w, c.w, a0);
            a1 = fmaf(e1.x, c.x, a1); a1 = fmaf(e1.y, c.y, a1);
            a1 = fmaf(e1.z, c.z, a1); a1 = fmaf(e1.w, c.w, a1);
            a2 = fmaf(e2.x, c.x, a2); a2 = fmaf(e2.y, c.y, a2);
            a2 = fmaf(e2.z, c.z, a2); a2 = fmaf(e2.w, c.w, a2);
            a3 = fmaf(e3.x, c.x, a3); a3 = fmaf(e3.y, c.y, a3);
            a3 = fmaf(e3.z, c.z, a3); a3 = fmaf(e3.w, c.w, a3);
        }
        const float v0 = scale * a0;
        const float v1 = scale * a1;
        const float v2 = scale * a2;
        const float v3 = scale * a3;
        float* o1 = out + b * 10000;
        float* o2 = out + 40000 + b * 10000;
        o1[(n0 + 0) * 100 + t] = v0;
        o1[(n0 + 1) * 100 + t] = v1;
        o1[(n0 + 2) * 100 + t] = v2;
        o1[(n0 + 3) * 100 + t] = v3;
        o2[t * 100 + n0 + 0] = v0;
        o2[t * 100 + n0 + 1] = v1;
        o2[t * 100 + n0 + 2] = v2;
        o2[t * 100 + n0 + 3] = v3;
    }
}

// ---------------------------------------------------------------------------
// Inputs: feat_c1, feat_c2, mask_c1, img_conv_w, img_conv_b, img_w1, img_w2,
// img_ln_g, img_ln_b, depth_conv_w, depth_conv_b, depth_w1, depth_w2,
// depth_ln_g, depth_ln_b, logit_scale
// ---------------------------------------------------------------------------
extern "C" void kernel_launch(void* const* d_in, const int* in_sizes, int n_in,
                              void* d_out, int out_size)
{
    cudaFuncSetAttribute(mlp_kernel, cudaFuncAttributeMaxDynamicSharedMemorySize,
                         MLP_SMEM_BYTES);

    conv_kernel<<<800, 256>>>((const float*)d_in[0], (const float*)d_in[1],
                              (const float*)d_in[3],  (const float*)d_in[4],
                              (const float*)d_in[9],  (const float*)d_in[10]);

    mlp_kernel<<<100, 256, MLP_SMEM_BYTES>>>(
                             (const float*)d_in[5],  (const float*)d_in[6],
                             (const float*)d_in[7],  (const float*)d_in[8],
                             (const float*)d_in[11], (const float*)d_in[12],
                             (const float*)d_in[13], (const float*)d_in[14]);

    logits_kernel<<<dim3(25, 4), 128>>>((const float*)d_in[15], (float*)d_out);
}

// round 12
// speedup vs baseline: 1.3428x; 1.0353x over previous
#include <cuda_runtime.h>

// Fixed shapes: B=4, C=256, H=W=160, CPS=16 -> nv=nh=10, N=100, NPAT=400/branch
#define HH   160
#define WW   160
#define CC   256
#define NPAT 400
#define ENC  128

__device__ float g_conv_out[2 * NPAT * 256];   // [branch][patch][pix]
__device__ float g_emb[2 * NPAT * ENC];        // [branch][patch][enc]
__device__ unsigned g_cnt;                     // monotonic barrier ticket counter

// ---------------------------------------------------------------------------
// Kernel A: channel-reduce conv + bias + relu. K split 4 ways (measured best:
// 34.4us @ 78.5% DRAM). 800 blocks x 256 threads; block = 64 f4 outputs.
// ---------------------------------------------------------------------------
__global__ void __launch_bounds__(256) conv_kernel(
    const float* __restrict__ f1, const float* __restrict__ f2,
    const float* __restrict__ w_img, const float* __restrict__ b_img,
    const float* __restrict__ w_dep, const float* __restrict__ b_dep)
{
    __shared__ float  ws[256];
    __shared__ float4 part[4][64];
    __shared__ float  bias_s;

    const int t      = threadIdx.x;
    const int branch = blockIdx.x / 400;
    const int item0  = (blockIdx.x % 400) * 64;

    const float* wsrc = branch ? w_dep : w_img;
    ws[t] = wsrc[t];
    if (t == 0) bias_s = branch ? b_dep[0] : b_img[0];
    __syncthreads();

    const int kg = t >> 6;        // channel group 0..3
    const int ol = t & 63;
    const int r  = item0 + ol;    // 0..25599 (float4 items per branch)
    const int b  = r / 6400;      // 160*40 float4 per image
    const int r2 = r % 6400;
    const int h  = r2 / 40;
    const int w0 = (r2 % 40) * 4;

    const float* feat  = branch ? f2 : f1;
    const float4* base = (const float4*)(feat + (size_t)b * CC * HH * WW + h * WW + w0)
                         + (size_t)kg * 64 * 6400;   // channel stride = 6400 f4

    float4 acc = make_float4(0.f, 0.f, 0.f, 0.f);
    #pragma unroll 16
    for (int c = 0; c < 64; c++) {
        float4 v = base[c * 6400];
        float wc = ws[kg * 64 + c];
        acc.x = fmaf(v.x, wc, acc.x);
        acc.y = fmaf(v.y, wc, acc.y);
        acc.z = fmaf(v.z, wc, acc.z);
        acc.w = fmaf(v.w, wc, acc.w);
    }
    part[kg][ol] = acc;
    __syncthreads();

    if (t < 64) {
        float4 p0 = part[0][t], p1 = part[1][t], p2 = part[2][t], p3 = part[3][t];
        const float bb = bias_s;
        float4 o4;
        o4.x = fmaxf(p0.x + p1.x + p2.x + p3.x + bb, 0.f);
        o4.y = fmaxf(p0.y + p1.y + p2.y + p3.y + bb, 0.f);
        o4.z = fmaxf(p0.z + p1.z + p2.z + p3.z + bb, 0.f);
        o4.w = fmaxf(p0.w + p1.w + p2.w + p3.w + bb, 0.f);

        const int rr  = item0 + t;
        const int bb2 = rr / 6400;
        const int rr2 = rr % 6400;
        const int hh  = rr2 / 40;
        const int ww0 = (rr2 % 40) * 4;
        const int p   = bb2 * 100 + (hh >> 4) * 10 + (ww0 >> 4);
        const int pix = (hh & 15) * 16 + (ww0 & 15);
        *(float4*)&g_conv_out[(size_t)branch * NPAT * 256 + p * 256 + pix] = o4;
    }
}

// ---------------------------------------------------------------------------
// Kernel B: fused MLP + LayerNorm + grid-barrier + logits.
// 100 blocks x 256 threads; smem 180KB -> 1 block/SM -> 100 blocks <= 148 SMs
// -> ALL blocks co-resident in wave 1 -> spin barrier is deadlock-free.
// Phase M: 3 GEMM phases (W1 lo/hi, W2) + LN (identical to measured R10 mlp).
// Barrier: monotonic ticket counter (never reset -> graph-replay safe).
// Phase L: logits, block i -> batch i/25, n0=(i%25)*4 (measured-best form).
// smem floats: ws 32768 | asT 3072 | h1T 3072 | red 5120 | ys 1056
// (phase L reuses red[] for e1s)
// ---------------------------------------------------------------------------
#define MLP_SMEM_FLOATS (32768 + 3072 + 3072 + 5120 + 1056)
#define MLP_SMEM_BYTES  (MLP_SMEM_FLOATS * 4)

__global__ void __launch_bounds__(256) tail_kernel(
    const float* __restrict__ w1_img, const float* __restrict__ w2_img,
    const float* __restrict__ g_img,  const float* __restrict__ be_img,
    const float* __restrict__ w1_dep, const float* __restrict__ w2_dep,
    const float* __restrict__ g_dep,  const float* __restrict__ be_dep,
    const float* __restrict__ logit_scale, float* __restrict__ out)
{
    extern __shared__ float sm[];
    float* ws_ = sm;                       // [256][128] swizzled weight tile
    float* asT = sm + 32768;               // [256][12]  x transposed
    float* h1T = sm + 32768 + 3072;        // [256][12]  h1 transposed
    float* red = sm + 32768 + 6144;        // [256][20]; reused as e1s in phase L
    float* ys  = sm + 32768 + 6144 + 5120; // [8][132]

    const int t      = threadIdx.x;
    const int branch = blockIdx.x / 50;
    const int p0     = blockIdx.x * 8;     // global patch base (0..792)

    const float* w1 = branch ? w1_dep : w1_img;
    const float* w2 = branch ? w2_dep : w2_img;

    // --- load asT[k][p] from g_conv_out (8 patches x 256) ---
    #pragma unroll
    for (int j = 0; j < 2; j++) {
        const int idx4 = j * 256 + t;      // 0..511
        const int p    = idx4 >> 6;        // 0..7
        const int k4   = idx4 & 63;
        float4 v = *(const float4*)&g_conv_out[(size_t)(p0 + p) * 256 + k4 * 4];
        asT[(k4 * 4 + 0) * 12 + p] = v.x;
        asT[(k4 * 4 + 1) * 12 + p] = v.y;
        asT[(k4 * 4 + 2) * 12 + p] = v.z;
        asT[(k4 * 4 + 3) * 12 + p] = v.w;
    }

    const int ox = t & 31;         // 4 outputs  ox*4..ox*4+3
    const int pg = (t >> 5) & 1;   // patches pg*4..pg*4+3
    const int kq = t >> 6;         // k-quarter

    #pragma unroll 1
    for (int phase = 0; phase < 3; phase++) {
        const float* wsrc = (phase == 0) ? w1 : (phase == 1 ? w1 + 128 * 256 : w2);

        // --- stream 128x256 weight tile, 4x4 reg transpose, swizzled store ---
        {
            const int k4 = t & 63;
            const int og = t >> 6;   // 0..3
            #pragma unroll
            for (int j = 0; j < 8; j++) {
                const int ob = og * 32 + j * 4;
                const int o4 = og * 8 + j;     // 0..31
                float4 v0 = *(const float4*)&wsrc[(size_t)(ob + 0) * 256 + k4 * 4];
                float4 v1 = *(const float4*)&wsrc[(size_t)(ob + 1) * 256 + k4 * 4];
                float4 v2 = *(const float4*)&wsrc[(size_t)(ob + 2) * 256 + k4 * 4];
                float4 v3 = *(const float4*)&wsrc[(size_t)(ob + 3) * 256 + k4 * 4];
                float4 t0 = make_float4(v0.x, v1.x, v2.x, v3.x);
                float4 t1 = make_float4(v0.y, v1.y, v2.y, v3.y);
                float4 t2 = make_float4(v0.z, v1.z, v2.z, v3.z);
                float4 t3 = make_float4(v0.w, v1.w, v2.w, v3.w);
                const int kb = k4 * 4;
                *(float4*)&ws_[(kb + 0) * 128 + ((o4 ^ ((kb + 0) & 31)) << 2)] = t0;
                *(float4*)&ws_[(kb + 1) * 128 + ((o4 ^ ((kb + 1) & 31)) << 2)] = t1;
                *(float4*)&ws_[(kb + 2) * 128 + ((o4 ^ ((kb + 2) & 31)) << 2)] = t2;
                *(float4*)&ws_[(kb + 3) * 128 + ((o4 ^ ((kb + 3) & 31)) << 2)] = t3;
            }
        }
        __syncthreads();

        // --- compute: 4 outs x 4 patches over this thread's 64-k quarter ---
        const float* xsrc = (phase < 2) ? asT : h1T;
        float a00 = 0.f, a01 = 0.f, a02 = 0.f, a03 = 0.f;
        float a10 = 0.f, a11 = 0.f, a12 = 0.f, a13 = 0.f;
        float a20 = 0.f, a21 = 0.f, a22 = 0.f, a23 = 0.f;
        float a30 = 0.f, a31 = 0.f, a32 = 0.f, a33 = 0.f;
        const int kbase = kq * 64;
        #pragma unroll 8
        for (int kk = 0; kk < 64; kk++) {
            const int k = kbase + kk;
            const float4 wv = *(const float4*)&ws_[k * 128 + ((ox ^ (k & 31)) << 2)];
            const float4 xv = *(const float4*)&xsrc[k * 12 + pg * 4];   // broadcast
            a00 = fmaf(wv.x, xv.x, a00); a01 = fmaf(wv.x, xv.y, a01);
            a02 = fmaf(wv.x, xv.z, a02); a03 = fmaf(wv.x, xv.w, a03);
            a10 = fmaf(wv.y, xv.x, a10); a11 = fmaf(wv.y, xv.y, a11);
            a12 = fmaf(wv.y, xv.z, a12); a13 = fmaf(wv.y, xv.w, a13);
            a20 = fmaf(wv.z, xv.x, a20); a21 = fmaf(wv.z, xv.y, a21);
            a22 = fmaf(wv.z, xv.z, a22); a23 = fmaf(wv.z, xv.w, a23);
            a30 = fmaf(wv.w, xv.x, a30); a31 = fmaf(wv.w, xv.y, a31);
            a32 = fmaf(wv.w, xv.z, a32); a33 = fmaf(wv.w, xv.w, a33);
        }
        *(float4*)&red[t * 20 +  0] = make_float4(a00, a01, a02, a03);
        *(float4*)&red[t * 20 +  4] = make_float4(a10, a11, a12, a13);
        *(float4*)&red[t * 20 +  8] = make_float4(a20, a21, a22, a23);
        *(float4*)&red[t * 20 + 12] = make_float4(a30, a31, a32, a33);
        __syncthreads();

        // --- combine k-quarters: 1024 outputs, 4 per thread ---
        #pragma unroll
        for (int rr = 0; rr < 4; rr++) {
            const int fidx = rr * 256 + t;       // 0..1023
            const int hi   = fidx >> 4;          // pg*32 + ox  (0..63)
            const int lo   = fidx & 15;          // oi*4 + pi
            float s = red[(0 * 64 + hi) * 20 + lo]
                    + red[(1 * 64 + hi) * 20 + lo]
                    + red[(2 * 64 + hi) * 20 + lo]
                    + red[(3 * 64 + hi) * 20 + lo];
            const int o = (hi & 31) * 4 + (lo >> 2);    // 0..127
            const int p = (hi >> 5) * 4 + (lo & 3);     // 0..7
            if (phase == 0)      h1T[o * 12 + p]         = fmaxf(s, 0.f);
            else if (phase == 1) h1T[(128 + o) * 12 + p] = fmaxf(s, 0.f);
            else                 ys[p * 132 + o]         = s;
        }
        __syncthreads();
    }

    // --- LayerNorm: warp w -> patch w ---
    {
        const int wid  = t >> 5;
        const int lane = t & 31;
        const float* yr = ys + wid * 132;
        float v0 = yr[lane], v1 = yr[lane + 32], v2 = yr[lane + 64], v3 = yr[lane + 96];
        float s  = v0 + v1 + v2 + v3;
        float ss = v0 * v0 + v1 * v1 + v2 * v2 + v3 * v3;
        #pragma unroll
        for (int off = 16; off > 0; off >>= 1) {
            s  += __shfl_xor_sync(0xffffffffu, s,  off);
            ss += __shfl_xor_sync(0xffffffffu, ss, off);
        }
        const float mean = s * (1.f / 128.f);
        const float var  = ss * (1.f / 128.f) - mean * mean;
        const float rstd = rsqrtf(var + 1e-5f);
        const float* lg = branch ? g_dep  : g_img;
        const float* lb = branch ? be_dep : be_img;
        float* outp = g_emb + (size_t)(p0 + wid) * 128;
        outp[lane]      = (v0 - mean) * rstd * lg[lane]      + lb[lane];
        outp[lane + 32] = (v1 - mean) * rstd * lg[lane + 32] + lb[lane + 32];
        outp[lane + 64] = (v2 - mean) * rstd * lg[lane + 64] + lb[lane + 64];
        outp[lane + 96] = (v3 - mean) * rstd * lg[lane + 96] + lb[lane + 96];
    }
    __syncthreads();

    // --- grid barrier (monotonic tickets; all 100 blocks co-resident) ---
    if (t == 0) {
        __threadfence();                                   // release g_emb writes
        unsigned ticket = atomicAdd(&g_cnt, 1u) + 1u;
        unsigned target = ((ticket + 99u) / 100u) * 100u;  // end of this launch's batch
        while (true) {
            unsigned cur;
            asm volatile("ld.volatile.global.u32 %0, [%1];"
                         : "=r"(cur) : "l"(&g_cnt) : "memory");
            if (cur >= target) break;
            __nanosleep(64);
        }
        __threadfence();                                   // acquire
    }
    __syncthreads();

    // --- Phase L: logits (measured-best form). Block i -> b=i/25, n0=(i%25)*4.
    {
        float (*e1s)[128] = (float(*)[128])red;   // reuse red as e1s[4][128]
        const int b  = blockIdx.x / 25;
        const int n0 = (blockIdx.x % 25) * 4;

        if (t < 128) {
            const int r  = t >> 5;
            const int c4 = t & 31;
            *(float4*)&e1s[r][c4 * 4] =
                *(const float4*)&g_emb[(size_t)(b * 100 + n0 + r) * 128 + c4 * 4];
        }
        __syncthreads();

        if (t < 100) {
            const float scale = expf(logit_scale[0]);
            const float4* e2r = (const float4*)&g_emb[(size_t)(NPAT + b * 100 + t) * 128];
            float a0 = 0.f, a1 = 0.f, a2 = 0.f, a3 = 0.f;
            #pragma unroll 8
            for (int d4 = 0; d4 < 32; d4++) {
                const float4 c  = e2r[d4];
                const float4 e0 = *(const float4*)&e1s[0][d4 * 4];
                const float4 e1 = *(const float4*)&e1s[1][d4 * 4];
                const float4 e2 = *(const float4*)&e1s[2][d4 * 4];
                const float4 e3 = *(const float4*)&e1s[3][d4 * 4];
                a0 = fmaf(e0.x, c.x, a0); a0 = fmaf(e0.y, c.y, a0);
                a0 = fmaf(e0.z, c.z, a0); a0 = fmaf(e0.w, c.w, a0);
                a1 = fmaf(e1.x, c.x, a1); a1 = fmaf(e1.y, c.y, a1);
                a1 = fmaf(e1.z, c.z, a1); a1 = fmaf(e1.w, c.w, a1);
                a2 = fmaf(e2.x, c.x, a2); a2 = fmaf(e2.y, c.y, a2);
                a2 = fmaf(e2.z, c.z, a2); a2 = fmaf(e2.w, c.w, a2);
                a3 = fmaf(e3.x, c.x, a3); a3 = fmaf(e3.y, c.y, a3);
                a3 = fmaf(e3.z, c.z, a3); a3 = fmaf(e3.w, c.w, a3);
            }
            const float v0 = scale * a0;
            const float v1 = scale * a1;
            const float v2 = scale * a2;
            const float v3 = scale * a3;
            float* o1 = out + b * 10000;
            float* o2 = out + 40000 + b * 10000;
            o1[(n0 + 0) * 100 + t] = v0;
            o1[(n0 + 1) * 100 + t] = v1;
            o1[(n0 + 2) * 100 + t] = v2;
            o1[(n0 + 3) * 100 + t] = v3;
            o2[t * 100 + n0 + 0] = v0;
            o2[t * 100 + n0 + 1] = v1;
            o2[t * 100 + n0 + 2] = v2;
            o2[t * 100 + n0 + 3] = v3;
        }
    }
}

// ---------------------------------------------------------------------------
// Inputs: feat_c1, feat_c2, mask_c1, img_conv_w, img_conv_b, img_w1, img_w2,
// img_ln_g, img_ln_b, depth_conv_w, depth_conv_b, depth_w1, depth_w2,
// depth_ln_g, depth_ln_b, logit_scale
// ---------------------------------------------------------------------------
extern "C" void kernel_launch(void* const* d_in, const int* in_sizes, int n_in,
                              void* d_out, int out_size)
{
    cudaFuncSetAttribute(tail_kernel, cudaFuncAttributeMaxDynamicSharedMemorySize,
                         MLP_SMEM_BYTES);

    conv_kernel<<<800, 256>>>((const float*)d_in[0], (const float*)d_in[1],
                              (const float*)d_in[3],  (const float*)d_in[4],
                              (const float*)d_in[9],  (const float*)d_in[10]);

    tail_kernel<<<100, 256, MLP_SMEM_BYTES>>>(
                             (const float*)d_in[5],  (const float*)d_in[6],
                             (const float*)d_in[7],  (const float*)d_in[8],
                             (const float*)d_in[11], (const float*)d_in[12],
                             (const float*)d_in[13], (const float*)d_in[14],
                             (const float*)d_in[15], (float*)d_out);
}